// round 13
// baseline (speedup 1.0000x reference)
#include <cuda_runtime.h>
#include <cuda_fp16.h>
#include <cstddef>
#include <cstdint>

// ---------------- Problem constants ----------------
#define NNODES   131072        // B*2*NN
#define HDIM     256
#define EMBD     64
#define NEDGE    1000000
#define NGROUP   2048          // B*2
#define CARD     100

// ---------------- Scratch (no allocs allowed) ----------------
__device__ __align__(16) __half g_h0 [NNODES * EMBD];
__device__ __align__(16) __half g_hA [NNODES * HDIM];  // ping
__device__ __align__(16) __half g_hB [NNODES * HDIM];  // pong
__device__ int   g_deg[NNODES + 1];
__device__ int   g_off[NNODES + 1];
__device__ int   g_cur[NNODES];
__device__ int   g_srcl[NEDGE];
// fp16 fragment-ordered weights: per k16 block: 256 cols x 4 tg, uint2 {lo-pair, hi-pair}
__device__ uint2 g_wf16[(4 + 16 + 16 + 16) * 1024];

// ---------------- Helpers ----------------
__device__ __forceinline__ uint32_t h2u(__half2 h) {
    return *reinterpret_cast<uint32_t*>(&h);
}
__device__ __forceinline__ float2 u2f2(uint32_t u) {
    return __half22float2(*reinterpret_cast<__half2*>(&u));
}

__device__ __forceinline__ void mma_f16(float (&c)[4], const uint4& a,
                                        uint32_t b0, uint32_t b1) {
    asm volatile(
        "mma.sync.aligned.m16n8k16.row.col.f32.f16.f16.f32 "
        "{%0,%1,%2,%3}, {%4,%5,%6,%7}, {%8,%9}, {%0,%1,%2,%3};"
        : "+f"(c[0]), "+f"(c[1]), "+f"(c[2]), "+f"(c[3])
        : "r"(a.x), "r"(a.y), "r"(a.z), "r"(a.w), "r"(b0), "r"(b1));
}

// ---------------- Weight pre-convert: [K,256] fp32 -> fp16 fragment order ----------------
__global__ void wcvt16_kernel(const float* __restrict__ W, uint2* __restrict__ out,
                              int k16count)
{
    int idx = blockIdx.x * blockDim.x + threadIdx.x;
    if (idx >= k16count * 1024) return;
    int tg  = idx & 3;
    int col = (idx >> 2) & 255;
    int k16 = idx >> 10;
    int kr  = k16 * 16;
    __half2 lo = __floats2half2_rn(W[(kr + 2 * tg)     * 256 + col],
                                   W[(kr + 2 * tg + 1) * 256 + col]);
    __half2 hi = __floats2half2_rn(W[(kr + 2 * tg + 8) * 256 + col],
                                   W[(kr + 2 * tg + 9) * 256 + col]);
    out[idx] = make_uint2(h2u(lo), h2u(hi));
}

// ---------------- Embedding gather (fp32 table -> fp16 h0) ----------------
__global__ void embed_kernel(const int* __restrict__ x,
                             const float* __restrict__ table,
                             __half* __restrict__ h0)
{
    int idx = blockIdx.x * blockDim.x + threadIdx.x;   // NNODES * 8 (8 halves each)
    if (idx >= NNODES * 8) return;
    int n  = idx >> 3;
    int c8 = idx & 7;
    int b   = n >> 7;
    int col = n & 127;
    int row = x[(b << 7) + col] + col * CARD;
    const float4* src = (const float4*)(table + (size_t)row * 64) + c8 * 2;
    float4 a = __ldg(src);
    float4 c = __ldg(src + 1);
    uint4 o;
    o.x = h2u(__floats2half2_rn(a.x, a.y));
    o.y = h2u(__floats2half2_rn(a.z, a.w));
    o.z = h2u(__floats2half2_rn(c.x, c.y));
    o.w = h2u(__floats2half2_rn(c.z, c.w));
    ((uint4*)h0)[idx] = o;
}

// ---------------- CSR build ----------------
__global__ void hist_kernel(const int* __restrict__ ei, int* __restrict__ deg)
{
    int e = blockIdx.x * blockDim.x + threadIdx.x;
    if (e < NEDGE) atomicAdd(deg + ei[NEDGE + e], 1);
}

__global__ void scan_kernel(const int* __restrict__ deg,
                            int* __restrict__ off, int* __restrict__ cur)
{
    __shared__ int ps[1024];
    const int t = threadIdx.x;
    const int base = t * 128;
    int s = 0;
#pragma unroll 8
    for (int i = 0; i < 128; i++) s += deg[base + i];
    ps[t] = s;
    __syncthreads();
    for (int o = 1; o < 1024; o <<= 1) {
        int v = (t >= o) ? ps[t - o] : 0;
        __syncthreads();
        ps[t] += v;
        __syncthreads();
    }
    int run = ps[t] - s;
#pragma unroll 8
    for (int i = 0; i < 128; i++) {
        int d = deg[base + i];
        off[base + i] = run;
        cur[base + i] = run;
        run += d;
    }
    if (t == 1023) off[NNODES] = run;
}

__global__ void fill_kernel(const int* __restrict__ ei,
                            int* __restrict__ cur, int* __restrict__ srcl)
{
    int e = blockIdx.x * blockDim.x + threadIdx.x;
    if (e >= NEDGE) return;
    int d = ei[NEDGE + e];
    int pos = atomicAdd(cur + d, 1);
    srcl[pos] = ei[e];
}

// ---------------- Fused GIN layer: gather + GEMM1 + LN + GEMM2 (+group reduce) ----
// Block = 512 threads = 16 warps; 64 rows x 256 cols. Warp w owns cols [w*16, w*16+16).
// hin and hout are DISTINCT buffers (ping-pong) — cross-block neighbor reads must
// never observe this layer's writes.
// Staging: 8 threads/node gather z = (1+eps)*h[node] + sum_nbr h[s] (fp32 acc)
//          and write fp16 mma fragments directly into Af.
// LN: per-warp column partials -> smem table -> per-row mean/inv -> each warp
//     normalizes its C in registers, writes fragments back to Af. No Ts buffer.
// FINAL: epilogue reduces C over the block's 64 rows (one group) -> fp32 d_out.

// SMEM float offsets
#define SPBA   0
#define SPG    256
#define SPB    512
#define AF_OFF 768                  // 8448 words (16 k16 * 4 mt * 33-pad * 4)
#define PS_OFF (768 + 8448)         // 1024 (64 rows x 16 warps)
#define PQ_OFF (PS_OFF + 1024)      // 1024
#define MR_OFF (PQ_OFF + 1024)      // 64
#define IR_OFF (MR_OFF + 64)        // 64
#define GIN_SMEM_F (IR_OFF + 64)

template<int K, bool FINAL>
__global__ void __launch_bounds__(512)
gin_f16_kernel(const int* __restrict__ off, const int* __restrict__ srcl,
               const __half* __restrict__ hin,
               const uint2* __restrict__ Waf, const float* __restrict__ ba,
               const float* __restrict__ gam,  const float* __restrict__ bet,
               const uint2* __restrict__ Wbf, const float* __restrict__ bb,
               const float* __restrict__ epsArr, int layer,
               __half* __restrict__ hout, float* __restrict__ gout)
{
    extern __shared__ float smem[];
    uint32_t* AfU = (uint32_t*)(smem + AF_OFF);

    const int t    = threadIdx.x;
    const int lane = t & 31;
    const int warp = t >> 5;
    const int g    = lane >> 2;
    const int tg   = lane & 3;
    const int wb   = warp * 16;
    const int rowBase = blockIdx.x * 64;

    if (t < 256) { smem[SPBA + t] = ba[t]; smem[SPG + t] = gam[t]; smem[SPB + t] = bet[t]; }

    // ---- Fused gather + stage Af fragments ----
    {
        constexpr int U4R = K / 8;              // uint4 per feature row
        const uint4* hu = (const uint4*)hin;
        const int sub  = t & 7;                 // 8 threads per node
        const int zrow = t >> 3;                // 0..63
        const int node = rowBase + zrow;
        const int beg = __ldg(off + node), end = __ldg(off + node + 1);
        const float ope = 1.0f + __ldg(epsArr + layer);
        const int mtz = zrow >> 4, rz = zrow & 15, g2z = rz & 7, qrz = rz >> 3;
#pragma unroll
        for (int j = 0; j < U4R / 8; j++) {
            int pos = sub + 8 * j;
            float a[8];
            {
                uint4 v = __ldg(hu + (size_t)node * U4R + pos);
#pragma unroll
                for (int u = 0; u < 4; u++) {
                    float2 f = u2f2((&v.x)[u]);
                    a[2 * u] = ope * f.x; a[2 * u + 1] = ope * f.y;
                }
            }
            int p = beg;
            for (; p + 4 <= end; p += 4) {      // 4 independent loads in flight
                int s0 = __ldg(srcl + p);
                int s1 = __ldg(srcl + p + 1);
                int s2 = __ldg(srcl + p + 2);
                int s3 = __ldg(srcl + p + 3);
                uint4 v0 = __ldg(hu + (size_t)s0 * U4R + pos);
                uint4 v1 = __ldg(hu + (size_t)s1 * U4R + pos);
                uint4 v2 = __ldg(hu + (size_t)s2 * U4R + pos);
                uint4 v3 = __ldg(hu + (size_t)s3 * U4R + pos);
#pragma unroll
                for (int u = 0; u < 4; u++) {
                    float2 f0 = u2f2((&v0.x)[u]), f1 = u2f2((&v1.x)[u]);
                    float2 f2 = u2f2((&v2.x)[u]), f3 = u2f2((&v3.x)[u]);
                    a[2 * u]     += (f0.x + f1.x) + (f2.x + f3.x);
                    a[2 * u + 1] += (f0.y + f1.y) + (f2.y + f3.y);
                }
            }
            for (; p < end; p++) {
                uint4 v = __ldg(hu + (size_t)__ldg(srcl + p) * U4R + pos);
#pragma unroll
                for (int u = 0; u < 4; u++) {
                    float2 f = u2f2((&v.x)[u]);
                    a[2 * u] += f.x; a[2 * u + 1] += f.y;
                }
            }
            int k16 = pos >> 1, hi = pos & 1;
            uint32_t* base = AfU + (((k16 * 4 + mtz) * 33) + g2z * 4) * 4 + qrz + 2 * hi;
            base[0]  = h2u(__floats2half2_rn(a[0], a[1]));
            base[4]  = h2u(__floats2half2_rn(a[2], a[3]));
            base[8]  = h2u(__floats2half2_rn(a[4], a[5]));
            base[12] = h2u(__floats2half2_rn(a[6], a[7]));
        }
    }
    __syncthreads();

    float C[4][2][4];
#pragma unroll
    for (int mt = 0; mt < 4; mt++)
#pragma unroll
        for (int nt = 0; nt < 2; nt++)
#pragma unroll
            for (int q = 0; q < 4; q++) C[mt][nt][q] = 0.0f;

    const int iA = (wb + g) * 4 + tg;
    const int iB = iA + 32;

    // ---- Phase 1: Af @ Waf ----
    {
        constexpr int K16 = K / 16;
        uint2 b0 = __ldg(Waf + iA);
        uint2 b1 = __ldg(Waf + iB);
#pragma unroll
        for (int k16 = 0; k16 < K16; k16++) {
            uint2 n0 = b0, n1 = b1;
            if (k16 + 1 < K16) {
                n0 = __ldg(Waf + (k16 + 1) * 1024 + iA);
                n1 = __ldg(Waf + (k16 + 1) * 1024 + iB);
            }
#pragma unroll
            for (int mt = 0; mt < 4; mt++) {
                uint4 a = *(const uint4*)(AfU + ((k16 * 4 + mt) * 33 + lane) * 4);
                mma_f16(C[mt][0], a, b0.x, b0.y);
                mma_f16(C[mt][1], a, b1.x, b1.y);
            }
            b0 = n0; b1 = n1;
        }
    }

    // ---- LN step 1: per-warp column partials over this warp's 16 cols ----
#pragma unroll
    for (int mt = 0; mt < 4; mt++)
#pragma unroll
        for (int qr = 0; qr < 2; qr++) {
            float s = 0.0f, q2 = 0.0f;
#pragma unroll
            for (int nt = 0; nt < 2; nt++)
#pragma unroll
                for (int lo = 0; lo < 2; lo++) {
                    int col = wb + nt * 8 + 2 * tg + lo;
                    float v = C[mt][nt][2 * qr + lo] + smem[SPBA + col];
                    s += v;
                    q2 = fmaf(v, v, q2);
                }
            s  += __shfl_xor_sync(0xffffffffu, s, 1);
            s  += __shfl_xor_sync(0xffffffffu, s, 2);
            q2 += __shfl_xor_sync(0xffffffffu, q2, 1);
            q2 += __shfl_xor_sync(0xffffffffu, q2, 2);
            if (tg == 0) {
                int row = mt * 16 + g + 8 * qr;
                smem[PS_OFF + row * 16 + warp] = s;
                smem[PQ_OFF + row * 16 + warp] = q2;
            }
        }
    __syncthreads();

    // ---- LN step 2: per-row stats (4 threads/row) ----
    if (t < 256) {
        int row = t >> 2;
        int p4  = t & 3;
        float s = 0.0f, q2 = 0.0f;
#pragma unroll
        for (int i = 0; i < 4; i++) {
            s  += smem[PS_OFF + row * 16 + p4 * 4 + i];
            q2 += smem[PQ_OFF + row * 16 + p4 * 4 + i];
        }
        s  += __shfl_xor_sync(0xffffffffu, s, 1);
        s  += __shfl_xor_sync(0xffffffffu, s, 2);
        q2 += __shfl_xor_sync(0xffffffffu, q2, 1);
        q2 += __shfl_xor_sync(0xffffffffu, q2, 2);
        if (p4 == 0) {
            float mean = s * (1.0f / 256.0f);
            float var  = q2 * (1.0f / 256.0f) - mean * mean;
            smem[MR_OFF + row] = mean;
            smem[IR_OFF + row] = rsqrtf(var + 1e-5f);
        }
    }
    __syncthreads();

    // ---- LN step 3: normalize in registers, write fragments to Af ----
#pragma unroll
    for (int mt = 0; mt < 4; mt++)
#pragma unroll
        for (int qr = 0; qr < 2; qr++) {
            int row = mt * 16 + g + 8 * qr;
            float mean = smem[MR_OFF + row];
            float inv  = smem[IR_OFF + row];
#pragma unroll
            for (int nt = 0; nt < 2; nt++) {
                int c0 = wb + nt * 8 + 2 * tg;
                float v0 = fmaf((C[mt][nt][2 * qr]     + smem[SPBA + c0]     - mean) * inv,
                                smem[SPG + c0],     smem[SPB + c0]);
                float v1 = fmaf((C[mt][nt][2 * qr + 1] + smem[SPBA + c0 + 1] - mean) * inv,
                                smem[SPG + c0 + 1], smem[SPB + c0 + 1]);
                v0 = fmaxf(v0, 0.0f);
                v1 = fmaxf(v1, 0.0f);
                AfU[((warp * 4 + mt) * 33 + g * 4 + tg) * 4 + qr + 2 * nt] =
                    h2u(__floats2half2_rn(v0, v1));
            }
        }
    __syncthreads();

    // ---- Phase 2: Af(=T) @ Wbf ----
#pragma unroll
    for (int mt = 0; mt < 4; mt++)
#pragma unroll
        for (int nt = 0; nt < 2; nt++)
#pragma unroll
            for (int q = 0; q < 4; q++) C[mt][nt][q] = 0.0f;

    {
        uint2 b0 = __ldg(Wbf + iA);
        uint2 b1 = __ldg(Wbf + iB);
#pragma unroll
        for (int k16 = 0; k16 < 16; k16++) {
            uint2 n0 = b0, n1 = b1;
            if (k16 + 1 < 16) {
                n0 = __ldg(Wbf + (k16 + 1) * 1024 + iA);
                n1 = __ldg(Wbf + (k16 + 1) * 1024 + iB);
            }
#pragma unroll
            for (int mt = 0; mt < 4; mt++) {
                uint4 a = *(const uint4*)(AfU + ((k16 * 4 + mt) * 33 + lane) * 4);
                mma_f16(C[mt][0], a, b0.x, b0.y);
                mma_f16(C[mt][1], a, b1.x, b1.y);
            }
            b0 = n0; b1 = n1;
        }
    }

    if (!FINAL) {
        // ---- + bb, store fp16 to global (distinct buffer from hin) ----
        uint32_t* ho = (uint32_t*)hout;
#pragma unroll
        for (int mt = 0; mt < 4; mt++)
#pragma unroll
            for (int nt = 0; nt < 2; nt++) {
                int r0  = rowBase + mt * 16 + g;
                int col = wb + nt * 8 + 2 * tg;
                float2 bbv = *(const float2*)(bb + col);
                __half2 o0 = __floats2half2_rn(C[mt][nt][0] + bbv.x, C[mt][nt][1] + bbv.y);
                __half2 o1 = __floats2half2_rn(C[mt][nt][2] + bbv.x, C[mt][nt][3] + bbv.y);
                ho[(size_t) r0      * 128 + (col >> 1)] = h2u(o0);
                ho[(size_t)(r0 + 8) * 128 + (col >> 1)] = h2u(o1);
            }
    } else {
        // ---- fused group reduction: sum over 64 rows, +64*bb, fp32 out ----
#pragma unroll
        for (int nt = 0; nt < 2; nt++) {
            float s0 = 0.0f, s1 = 0.0f;
#pragma unroll
            for (int mt = 0; mt < 4; mt++) {
                s0 += C[mt][nt][0] + C[mt][nt][2];
                s1 += C[mt][nt][1] + C[mt][nt][3];
            }
#pragma unroll
            for (int o = 4; o <= 16; o <<= 1) {
                s0 += __shfl_xor_sync(0xffffffffu, s0, o);
                s1 += __shfl_xor_sync(0xffffffffu, s1, o);
            }
            if (g == 0) {
                int col = wb + nt * 8 + 2 * tg;
                float2 bbv = *(const float2*)(bb + col);
                float2 o2 = make_float2(s0 + 64.0f * bbv.x, s1 + 64.0f * bbv.y);
                *(float2*)(gout + (size_t)blockIdx.x * 256 + col) = o2;
            }
        }
    }
}

// ---------------- Launch ----------------
extern "C" void kernel_launch(void* const* d_in, const int* in_sizes, int n_in,
                              void* d_out, int out_size)
{
    const int*   x     = (const int*)  d_in[0];
    const int*   ei    = (const int*)  d_in[1];
    const float* table = (const float*)d_in[3];
    const float* W0a   = (const float*)d_in[4];
    const float* b0a   = (const float*)d_in[5];
    const float* g0    = (const float*)d_in[6];
    const float* be0   = (const float*)d_in[7];
    const float* W0b   = (const float*)d_in[8];
    const float* b0b   = (const float*)d_in[9];
    const float* Wha   = (const float*)d_in[10];
    const float* bha   = (const float*)d_in[11];
    const float* gh    = (const float*)d_in[12];
    const float* beh   = (const float*)d_in[13];
    const float* Whb   = (const float*)d_in[14];
    const float* bhb   = (const float*)d_in[15];
    const float* eps   = (const float*)d_in[16];

    __half *h0, *hA, *hB;
    int *deg, *off, *cur, *srcl;
    uint2 *wf;
    cudaGetSymbolAddress((void**)&h0,   g_h0);
    cudaGetSymbolAddress((void**)&hA,   g_hA);
    cudaGetSymbolAddress((void**)&hB,   g_hB);
    cudaGetSymbolAddress((void**)&deg,  g_deg);
    cudaGetSymbolAddress((void**)&off,  g_off);
    cudaGetSymbolAddress((void**)&cur,  g_cur);
    cudaGetSymbolAddress((void**)&srcl, g_srcl);
    cudaGetSymbolAddress((void**)&wf,   g_wf16);

    uint2* W0af = wf;               // 4 k16 blocks
    uint2* W0bf = wf + 4  * 1024;   // 16
    uint2* Whaf = wf + 20 * 1024;   // 16
    uint2* Whbf = wf + 36 * 1024;   // 16

    const int SMEM_BYTES = GIN_SMEM_F * (int)sizeof(float);
    cudaFuncSetAttribute((const void*)gin_f16_kernel<64, false>,
                         cudaFuncAttributeMaxDynamicSharedMemorySize, SMEM_BYTES);
    cudaFuncSetAttribute((const void*)gin_f16_kernel<256, false>,
                         cudaFuncAttributeMaxDynamicSharedMemorySize, SMEM_BYTES);
    cudaFuncSetAttribute((const void*)gin_f16_kernel<256, true>,
                         cudaFuncAttributeMaxDynamicSharedMemorySize, SMEM_BYTES);

    // ---- Weight pre-convert (fp16 fragment order) ----
    wcvt16_kernel<<<(4  * 1024 + 255) / 256, 256>>>(W0a, W0af, 4);
    wcvt16_kernel<<<(16 * 1024 + 255) / 256, 256>>>(W0b, W0bf, 16);
    wcvt16_kernel<<<(16 * 1024 + 255) / 256, 256>>>(Wha, Whaf, 16);
    wcvt16_kernel<<<(16 * 1024 + 255) / 256, 256>>>(Whb, Whbf, 16);

    // ---- CSR build ----
    cudaMemsetAsync(deg, 0, (NNODES + 1) * sizeof(int));
    hist_kernel<<<(NEDGE + 255) / 256, 256>>>(ei, deg);
    scan_kernel<<<1, 1024>>>(deg, off, cur);
    fill_kernel<<<(NEDGE + 255) / 256, 256>>>(ei, cur, srcl);

    // ---- Embedding gather ----
    embed_kernel<<<(NNODES * 8 + 255) / 256, 256>>>(x, table, h0);

    // ---- Layer 0 (K = 64, gather fused): h0 -> hA ----
    gin_f16_kernel<64, false><<<NNODES / 64, 512, SMEM_BYTES>>>(
        off, srcl, h0, W0af, b0a, g0, be0, W0bf, b0b, eps, 0, hA, nullptr);

    // ---- Layer 1 (K = 256, gather fused): hA -> hB ----
    gin_f16_kernel<256, false><<<NNODES / 64, 512, SMEM_BYTES>>>(
        off, srcl, hA, Whaf, bha, gh, beh, Whbf, bhb, eps, 1, hB, nullptr);

    // ---- Layer 2 (K = 256): hB -> d_out (fused group reduction) ----
    gin_f16_kernel<256, true><<<NNODES / 64, 512, SMEM_BYTES>>>(
        off, srcl, hB, Whaf, bha, gh, beh, Whbf, bhb, eps, 2, nullptr, (float*)d_out);
}

// round 14
// speedup vs baseline: 1.0300x; 1.0300x over previous
#include <cuda_runtime.h>
#include <cuda_fp16.h>
#include <cstddef>
#include <cstdint>

// ---------------- Problem constants ----------------
#define NNODES   131072        // B*2*NN
#define HDIM     256
#define EMBD     64
#define NEDGE    1000000
#define NGROUP   2048          // B*2
#define CARD     100

// ---------------- Scratch (no allocs allowed) ----------------
__device__ __align__(16) __half g_h0 [NNODES * EMBD];
__device__ __align__(16) __half g_hA [NNODES * HDIM];  // ping
__device__ __align__(16) __half g_hB [NNODES * HDIM];  // pong
__device__ int   g_deg[NNODES + 1];
__device__ int   g_off[NNODES + 1];
__device__ int   g_cur[NNODES];
__device__ int   g_srcl[NEDGE];
// fp16 fragment-ordered weights: per k16 block: 256 cols x 4 tg, uint2 {lo-pair, hi-pair}
__device__ uint2 g_wf16[(4 + 16 + 16 + 16) * 1024];

// ---------------- Helpers ----------------
__device__ __forceinline__ uint32_t h2u(__half2 h) {
    return *reinterpret_cast<uint32_t*>(&h);
}
__device__ __forceinline__ float2 u2f2(uint32_t u) {
    return __half22float2(*reinterpret_cast<__half2*>(&u));
}

__device__ __forceinline__ void mma_f16(float (&c)[4], const uint4& a,
                                        uint32_t b0, uint32_t b1) {
    asm volatile(
        "mma.sync.aligned.m16n8k16.row.col.f32.f16.f16.f32 "
        "{%0,%1,%2,%3}, {%4,%5,%6,%7}, {%8,%9}, {%0,%1,%2,%3};"
        : "+f"(c[0]), "+f"(c[1]), "+f"(c[2]), "+f"(c[3])
        : "r"(a.x), "r"(a.y), "r"(a.z), "r"(a.w), "r"(b0), "r"(b1));
}

// ---------------- Weight pre-convert: [K,256] fp32 -> fp16 fragment order ----------------
__global__ void wcvt16_kernel(const float* __restrict__ W, uint2* __restrict__ out,
                              int k16count)
{
    int idx = blockIdx.x * blockDim.x + threadIdx.x;
    if (idx >= k16count * 1024) return;
    int tg  = idx & 3;
    int col = (idx >> 2) & 255;
    int k16 = idx >> 10;
    int kr  = k16 * 16;
    __half2 lo = __floats2half2_rn(W[(kr + 2 * tg)     * 256 + col],
                                   W[(kr + 2 * tg + 1) * 256 + col]);
    __half2 hi = __floats2half2_rn(W[(kr + 2 * tg + 8) * 256 + col],
                                   W[(kr + 2 * tg + 9) * 256 + col]);
    out[idx] = make_uint2(h2u(lo), h2u(hi));
}

// ---------------- Embedding gather (fp32 table -> fp16 h0) ----------------
__global__ void embed_kernel(const int* __restrict__ x,
                             const float* __restrict__ table,
                             __half* __restrict__ h0)
{
    int idx = blockIdx.x * blockDim.x + threadIdx.x;   // NNODES * 8 (8 halves each)
    if (idx >= NNODES * 8) return;
    int n  = idx >> 3;
    int c8 = idx & 7;
    int b   = n >> 7;
    int col = n & 127;
    int row = x[(b << 7) + col] + col * CARD;
    const float4* src = (const float4*)(table + (size_t)row * 64) + c8 * 2;
    float4 a = __ldg(src);
    float4 c = __ldg(src + 1);
    uint4 o;
    o.x = h2u(__floats2half2_rn(a.x, a.y));
    o.y = h2u(__floats2half2_rn(a.z, a.w));
    o.z = h2u(__floats2half2_rn(c.x, c.y));
    o.w = h2u(__floats2half2_rn(c.z, c.w));
    ((uint4*)h0)[idx] = o;
}

// ---------------- CSR build ----------------
__global__ void hist_kernel(const int* __restrict__ ei, int* __restrict__ deg)
{
    int e = blockIdx.x * blockDim.x + threadIdx.x;
    if (e < NEDGE) atomicAdd(deg + ei[NEDGE + e], 1);
}

__global__ void scan_kernel(const int* __restrict__ deg,
                            int* __restrict__ off, int* __restrict__ cur)
{
    __shared__ int ps[1024];
    const int t = threadIdx.x;
    const int base = t * 128;
    int s = 0;
#pragma unroll 8
    for (int i = 0; i < 128; i++) s += deg[base + i];
    ps[t] = s;
    __syncthreads();
    for (int o = 1; o < 1024; o <<= 1) {
        int v = (t >= o) ? ps[t - o] : 0;
        __syncthreads();
        ps[t] += v;
        __syncthreads();
    }
    int run = ps[t] - s;
#pragma unroll 8
    for (int i = 0; i < 128; i++) {
        int d = deg[base + i];
        off[base + i] = run;
        cur[base + i] = run;
        run += d;
    }
    if (t == 1023) off[NNODES] = run;
}

__global__ void fill_kernel(const int* __restrict__ ei,
                            int* __restrict__ cur, int* __restrict__ srcl)
{
    int e = blockIdx.x * blockDim.x + threadIdx.x;
    if (e >= NEDGE) return;
    int d = ei[NEDGE + e];
    int pos = atomicAdd(cur + d, 1);
    srcl[pos] = ei[e];
}

// ---------------- Fused GIN layer: gather + GEMM1 + LN + GEMM2 (+group reduce) ----
// Block = 512 threads = 16 warps; 64 rows x 256 cols. Warp w owns cols [w*16, w*16+16).
// hin/hout are DISTINCT buffers (ping-pong).
// Staging (K=256): WARP-UNIFORM — one node per warp iteration, 32 lanes = full row.
//   srcl reads broadcast, neighbor rows fetched as one coalesced 512B transaction,
//   degree loop uniform across the warp (no divergence), MLP=4 over neighbors.
// LN: per-warp column partials -> smem -> per-row stats -> normalize in regs -> Af.
// FINAL: epilogue reduces C over the block's 64 rows (one group) -> fp32 d_out.

// SMEM float offsets
#define SPBA   0
#define SPG    256
#define SPB    512
#define AF_OFF 768                  // 8448 words (16 k16 * 4 mt * 33-pad * 4)
#define PS_OFF (768 + 8448)         // 1024 (64 rows x 16 warps)
#define PQ_OFF (PS_OFF + 1024)      // 1024
#define MR_OFF (PQ_OFF + 1024)      // 64
#define IR_OFF (MR_OFF + 64)        // 64
#define GIN_SMEM_F (IR_OFF + 64)

template<int K, bool FINAL>
__global__ void __launch_bounds__(512)
gin_f16_kernel(const int* __restrict__ off, const int* __restrict__ srcl,
               const __half* __restrict__ hin,
               const uint2* __restrict__ Waf, const float* __restrict__ ba,
               const float* __restrict__ gam,  const float* __restrict__ bet,
               const uint2* __restrict__ Wbf, const float* __restrict__ bb,
               const float* __restrict__ epsArr, int layer,
               __half* __restrict__ hout, float* __restrict__ gout)
{
    extern __shared__ float smem[];
    uint32_t* AfU = (uint32_t*)(smem + AF_OFF);

    const int t    = threadIdx.x;
    const int lane = t & 31;
    const int warp = t >> 5;
    const int g    = lane >> 2;
    const int tg   = lane & 3;
    const int wb   = warp * 16;
    const int rowBase = blockIdx.x * 64;

    if (t < 256) { smem[SPBA + t] = ba[t]; smem[SPG + t] = gam[t]; smem[SPB + t] = bet[t]; }

    // ---- Fused gather + stage Af fragments (warp-uniform node loop) ----
    {
        constexpr int U4R = K / 8;                    // uint4 per feature row
        constexpr int TPN = (U4R < 32) ? U4R : 32;    // threads per node
        constexpr int NPW = 32 / TPN;                 // nodes handled concurrently
        constexpr int NI  = 4 / NPW;                  // serial node iterations per warp
        const uint4* hu = (const uint4*)hin;
        const int sub = lane % TPN;                   // uint4 position within row
        const int nwi = lane / TPN;                   // concurrent node slot
        const float ope = 1.0f + __ldg(epsArr + layer);
#pragma unroll
        for (int i = 0; i < NI; i++) {
            const int zrow = warp * 4 + i * NPW + nwi;
            const int node = rowBase + zrow;
            const int beg = __ldg(off + node), end = __ldg(off + node + 1);
            const int mtz = zrow >> 4, rz = zrow & 15, g2z = rz & 7, qrz = rz >> 3;
            const int pos = sub;                       // TPN == U4R covers row once
            float a[8];
            {
                uint4 v = __ldg(hu + (size_t)node * U4R + pos);
#pragma unroll
                for (int u = 0; u < 4; u++) {
                    float2 f = u2f2((&v.x)[u]);
                    a[2 * u] = ope * f.x; a[2 * u + 1] = ope * f.y;
                }
            }
            int p = beg;
            for (; p + 4 <= end; p += 4) {             // 4 independent rows in flight
                int s0 = __ldg(srcl + p);
                int s1 = __ldg(srcl + p + 1);
                int s2 = __ldg(srcl + p + 2);
                int s3 = __ldg(srcl + p + 3);
                uint4 v0 = __ldg(hu + (size_t)s0 * U4R + pos);
                uint4 v1 = __ldg(hu + (size_t)s1 * U4R + pos);
                uint4 v2 = __ldg(hu + (size_t)s2 * U4R + pos);
                uint4 v3 = __ldg(hu + (size_t)s3 * U4R + pos);
#pragma unroll
                for (int u = 0; u < 4; u++) {
                    float2 f0 = u2f2((&v0.x)[u]), f1 = u2f2((&v1.x)[u]);
                    float2 f2 = u2f2((&v2.x)[u]), f3 = u2f2((&v3.x)[u]);
                    a[2 * u]     += (f0.x + f1.x) + (f2.x + f3.x);
                    a[2 * u + 1] += (f0.y + f1.y) + (f2.y + f3.y);
                }
            }
            for (; p < end; p++) {
                uint4 v = __ldg(hu + (size_t)__ldg(srcl + p) * U4R + pos);
#pragma unroll
                for (int u = 0; u < 4; u++) {
                    float2 f = u2f2((&v.x)[u]);
                    a[2 * u] += f.x; a[2 * u + 1] += f.y;
                }
            }
            int k16 = pos >> 1, hi = pos & 1;
            uint32_t* base = AfU + (((k16 * 4 + mtz) * 33) + g2z * 4) * 4 + qrz + 2 * hi;
            base[0]  = h2u(__floats2half2_rn(a[0], a[1]));
            base[4]  = h2u(__floats2half2_rn(a[2], a[3]));
            base[8]  = h2u(__floats2half2_rn(a[4], a[5]));
            base[12] = h2u(__floats2half2_rn(a[6], a[7]));
        }
    }
    __syncthreads();

    float C[4][2][4];
#pragma unroll
    for (int mt = 0; mt < 4; mt++)
#pragma unroll
        for (int nt = 0; nt < 2; nt++)
#pragma unroll
            for (int q = 0; q < 4; q++) C[mt][nt][q] = 0.0f;

    const int iA = (wb + g) * 4 + tg;
    const int iB = iA + 32;

    // ---- Phase 1: Af @ Waf ----
    {
        constexpr int K16 = K / 16;
        uint2 b0 = __ldg(Waf + iA);
        uint2 b1 = __ldg(Waf + iB);
#pragma unroll
        for (int k16 = 0; k16 < K16; k16++) {
            uint2 n0 = b0, n1 = b1;
            if (k16 + 1 < K16) {
                n0 = __ldg(Waf + (k16 + 1) * 1024 + iA);
                n1 = __ldg(Waf + (k16 + 1) * 1024 + iB);
            }
#pragma unroll
            for (int mt = 0; mt < 4; mt++) {
                uint4 a = *(const uint4*)(AfU + ((k16 * 4 + mt) * 33 + lane) * 4);
                mma_f16(C[mt][0], a, b0.x, b0.y);
                mma_f16(C[mt][1], a, b1.x, b1.y);
            }
            b0 = n0; b1 = n1;
        }
    }

    // ---- LN step 1: per-warp column partials over this warp's 16 cols ----
#pragma unroll
    for (int mt = 0; mt < 4; mt++)
#pragma unroll
        for (int qr = 0; qr < 2; qr++) {
            float s = 0.0f, q2 = 0.0f;
#pragma unroll
            for (int nt = 0; nt < 2; nt++)
#pragma unroll
                for (int lo = 0; lo < 2; lo++) {
                    int col = wb + nt * 8 + 2 * tg + lo;
                    float v = C[mt][nt][2 * qr + lo] + smem[SPBA + col];
                    s += v;
                    q2 = fmaf(v, v, q2);
                }
            s  += __shfl_xor_sync(0xffffffffu, s, 1);
            s  += __shfl_xor_sync(0xffffffffu, s, 2);
            q2 += __shfl_xor_sync(0xffffffffu, q2, 1);
            q2 += __shfl_xor_sync(0xffffffffu, q2, 2);
            if (tg == 0) {
                int row = mt * 16 + g + 8 * qr;
                smem[PS_OFF + row * 16 + warp] = s;
                smem[PQ_OFF + row * 16 + warp] = q2;
            }
        }
    __syncthreads();

    // ---- LN step 2: per-row stats (4 threads/row) ----
    if (t < 256) {
        int row = t >> 2;
        int p4  = t & 3;
        float s = 0.0f, q2 = 0.0f;
#pragma unroll
        for (int i = 0; i < 4; i++) {
            s  += smem[PS_OFF + row * 16 + p4 * 4 + i];
            q2 += smem[PQ_OFF + row * 16 + p4 * 4 + i];
        }
        s  += __shfl_xor_sync(0xffffffffu, s, 1);
        s  += __shfl_xor_sync(0xffffffffu, s, 2);
        q2 += __shfl_xor_sync(0xffffffffu, q2, 1);
        q2 += __shfl_xor_sync(0xffffffffu, q2, 2);
        if (p4 == 0) {
            float mean = s * (1.0f / 256.0f);
            float var  = q2 * (1.0f / 256.0f) - mean * mean;
            smem[MR_OFF + row] = mean;
            smem[IR_OFF + row] = rsqrtf(var + 1e-5f);
        }
    }
    __syncthreads();

    // ---- LN step 3: normalize in registers, write fragments to Af ----
#pragma unroll
    for (int mt = 0; mt < 4; mt++)
#pragma unroll
        for (int qr = 0; qr < 2; qr++) {
            int row = mt * 16 + g + 8 * qr;
            float mean = smem[MR_OFF + row];
            float inv  = smem[IR_OFF + row];
#pragma unroll
            for (int nt = 0; nt < 2; nt++) {
                int c0 = wb + nt * 8 + 2 * tg;
                float v0 = fmaf((C[mt][nt][2 * qr]     + smem[SPBA + c0]     - mean) * inv,
                                smem[SPG + c0],     smem[SPB + c0]);
                float v1 = fmaf((C[mt][nt][2 * qr + 1] + smem[SPBA + c0 + 1] - mean) * inv,
                                smem[SPG + c0 + 1], smem[SPB + c0 + 1]);
                v0 = fmaxf(v0, 0.0f);
                v1 = fmaxf(v1, 0.0f);
                AfU[((warp * 4 + mt) * 33 + g * 4 + tg) * 4 + qr + 2 * nt] =
                    h2u(__floats2half2_rn(v0, v1));
            }
        }
    __syncthreads();

    // ---- Phase 2: Af(=T) @ Wbf ----
#pragma unroll
    for (int mt = 0; mt < 4; mt++)
#pragma unroll
        for (int nt = 0; nt < 2; nt++)
#pragma unroll
            for (int q = 0; q < 4; q++) C[mt][nt][q] = 0.0f;

    {
        uint2 b0 = __ldg(Wbf + iA);
        uint2 b1 = __ldg(Wbf + iB);
#pragma unroll
        for (int k16 = 0; k16 < 16; k16++) {
            uint2 n0 = b0, n1 = b1;
            if (k16 + 1 < 16) {
                n0 = __ldg(Wbf + (k16 + 1) * 1024 + iA);
                n1 = __ldg(Wbf + (k16 + 1) * 1024 + iB);
            }
#pragma unroll
            for (int mt = 0; mt < 4; mt++) {
                uint4 a = *(const uint4*)(AfU + ((k16 * 4 + mt) * 33 + lane) * 4);
                mma_f16(C[mt][0], a, b0.x, b0.y);
                mma_f16(C[mt][1], a, b1.x, b1.y);
            }
            b0 = n0; b1 = n1;
        }
    }

    if (!FINAL) {
        // ---- + bb, store fp16 to global (distinct buffer from hin) ----
        uint32_t* ho = (uint32_t*)hout;
#pragma unroll
        for (int mt = 0; mt < 4; mt++)
#pragma unroll
            for (int nt = 0; nt < 2; nt++) {
                int r0  = rowBase + mt * 16 + g;
                int col = wb + nt * 8 + 2 * tg;
                float2 bbv = *(const float2*)(bb + col);
                __half2 o0 = __floats2half2_rn(C[mt][nt][0] + bbv.x, C[mt][nt][1] + bbv.y);
                __half2 o1 = __floats2half2_rn(C[mt][nt][2] + bbv.x, C[mt][nt][3] + bbv.y);
                ho[(size_t) r0      * 128 + (col >> 1)] = h2u(o0);
                ho[(size_t)(r0 + 8) * 128 + (col >> 1)] = h2u(o1);
            }
    } else {
        // ---- fused group reduction: sum over 64 rows, +64*bb, fp32 out ----
#pragma unroll
        for (int nt = 0; nt < 2; nt++) {
            float s0 = 0.0f, s1 = 0.0f;
#pragma unroll
            for (int mt = 0; mt < 4; mt++) {
                s0 += C[mt][nt][0] + C[mt][nt][2];
                s1 += C[mt][nt][1] + C[mt][nt][3];
            }
#pragma unroll
            for (int o = 4; o <= 16; o <<= 1) {
                s0 += __shfl_xor_sync(0xffffffffu, s0, o);
                s1 += __shfl_xor_sync(0xffffffffu, s1, o);
            }
            if (g == 0) {
                int col = wb + nt * 8 + 2 * tg;
                float2 bbv = *(const float2*)(bb + col);
                float2 o2 = make_float2(s0 + 64.0f * bbv.x, s1 + 64.0f * bbv.y);
                *(float2*)(gout + (size_t)blockIdx.x * 256 + col) = o2;
            }
        }
    }
}

// ---------------- Launch ----------------
extern "C" void kernel_launch(void* const* d_in, const int* in_sizes, int n_in,
                              void* d_out, int out_size)
{
    const int*   x     = (const int*)  d_in[0];
    const int*   ei    = (const int*)  d_in[1];
    const float* table = (const float*)d_in[3];
    const float* W0a   = (const float*)d_in[4];
    const float* b0a   = (const float*)d_in[5];
    const float* g0    = (const float*)d_in[6];
    const float* be0   = (const float*)d_in[7];
    const float* W0b   = (const float*)d_in[8];
    const float* b0b   = (const float*)d_in[9];
    const float* Wha   = (const float*)d_in[10];
    const float* bha   = (const float*)d_in[11];
    const float* gh    = (const float*)d_in[12];
    const float* beh   = (const float*)d_in[13];
    const float* Whb   = (const float*)d_in[14];
    const float* bhb   = (const float*)d_in[15];
    const float* eps   = (const float*)d_in[16];

    __half *h0, *hA, *hB;
    int *deg, *off, *cur, *srcl;
    uint2 *wf;
    cudaGetSymbolAddress((void**)&h0,   g_h0);
    cudaGetSymbolAddress((void**)&hA,   g_hA);
    cudaGetSymbolAddress((void**)&hB,   g_hB);
    cudaGetSymbolAddress((void**)&deg,  g_deg);
    cudaGetSymbolAddress((void**)&off,  g_off);
    cudaGetSymbolAddress((void**)&cur,  g_cur);
    cudaGetSymbolAddress((void**)&srcl, g_srcl);
    cudaGetSymbolAddress((void**)&wf,   g_wf16);

    uint2* W0af = wf;               // 4 k16 blocks
    uint2* W0bf = wf + 4  * 1024;   // 16
    uint2* Whaf = wf + 20 * 1024;   // 16
    uint2* Whbf = wf + 36 * 1024;   // 16

    const int SMEM_BYTES = GIN_SMEM_F * (int)sizeof(float);
    cudaFuncSetAttribute((const void*)gin_f16_kernel<64, false>,
                         cudaFuncAttributeMaxDynamicSharedMemorySize, SMEM_BYTES);
    cudaFuncSetAttribute((const void*)gin_f16_kernel<256, false>,
                         cudaFuncAttributeMaxDynamicSharedMemorySize, SMEM_BYTES);
    cudaFuncSetAttribute((const void*)gin_f16_kernel<256, true>,
                         cudaFuncAttributeMaxDynamicSharedMemorySize, SMEM_BYTES);

    // ---- Weight pre-convert (fp16 fragment order) ----
    wcvt16_kernel<<<(4  * 1024 + 255) / 256, 256>>>(W0a, W0af, 4);
    wcvt16_kernel<<<(16 * 1024 + 255) / 256, 256>>>(W0b, W0bf, 16);
    wcvt16_kernel<<<(16 * 1024 + 255) / 256, 256>>>(Wha, Whaf, 16);
    wcvt16_kernel<<<(16 * 1024 + 255) / 256, 256>>>(Whb, Whbf, 16);

    // ---- CSR build ----
    cudaMemsetAsync(deg, 0, (NNODES + 1) * sizeof(int));
    hist_kernel<<<(NEDGE + 255) / 256, 256>>>(ei, deg);
    scan_kernel<<<1, 1024>>>(deg, off, cur);
    fill_kernel<<<(NEDGE + 255) / 256, 256>>>(ei, cur, srcl);

    // ---- Embedding gather ----
    embed_kernel<<<(NNODES * 8 + 255) / 256, 256>>>(x, table, h0);

    // ---- Layer 0 (K = 64, gather fused): h0 -> hA ----
    gin_f16_kernel<64, false><<<NNODES / 64, 512, SMEM_BYTES>>>(
        off, srcl, h0, W0af, b0a, g0, be0, W0bf, b0b, eps, 0, hA, nullptr);

    // ---- Layer 1 (K = 256, gather fused): hA -> hB ----
    gin_f16_kernel<256, false><<<NNODES / 64, 512, SMEM_BYTES>>>(
        off, srcl, hA, Whaf, bha, gh, beh, Whbf, bhb, eps, 1, hB, nullptr);

    // ---- Layer 2 (K = 256): hB -> d_out (fused group reduction) ----
    gin_f16_kernel<256, true><<<NNODES / 64, 512, SMEM_BYTES>>>(
        off, srcl, hB, Whaf, bha, gh, beh, Whbf, bhb, eps, 2, nullptr, (float*)d_out);
}

// round 16
// speedup vs baseline: 1.1842x; 1.1498x over previous
#include <cuda_runtime.h>
#include <cuda_fp16.h>
#include <cstddef>
#include <cstdint>

// ---------------- Problem constants ----------------
#define NNODES   131072        // B*2*NN
#define HDIM     256
#define EMBD     64
#define NEDGE    1000000
#define NGROUP   2048          // B*2
#define CARD     100

// ---------------- Scratch (no allocs allowed) ----------------
__device__ __align__(16) __half g_h0 [NNODES * EMBD];
__device__ __align__(16) __half g_hA [NNODES * HDIM];  // ping
__device__ __align__(16) __half g_hB [NNODES * HDIM];  // pong
__device__ int   g_deg[NNODES + 1];
__device__ int   g_off[NNODES + 1];
__device__ int   g_cur[NNODES];
__device__ int   g_srcl[NEDGE];
// fp16 fragment-ordered weights: per k16 block: 256 cols x 4 tg, uint2 {lo-pair, hi-pair}
__device__ uint2 g_wf16[(4 + 16 + 16 + 16) * 1024];

// ---------------- Helpers ----------------
__device__ __forceinline__ uint32_t h2u(__half2 h) {
    return *reinterpret_cast<uint32_t*>(&h);
}
__device__ __forceinline__ float2 u2f2(uint32_t u) {
    return __half22float2(*reinterpret_cast<__half2*>(&u));
}

__device__ __forceinline__ void mma_f16(float (&c)[4], const uint4& a,
                                        uint32_t b0, uint32_t b1) {
    asm volatile(
        "mma.sync.aligned.m16n8k16.row.col.f32.f16.f16.f32 "
        "{%0,%1,%2,%3}, {%4,%5,%6,%7}, {%8,%9}, {%0,%1,%2,%3};"
        : "+f"(c[0]), "+f"(c[1]), "+f"(c[2]), "+f"(c[3])
        : "r"(a.x), "r"(a.y), "r"(a.z), "r"(a.w), "r"(b0), "r"(b1));
}

// ---------------- Merged weight pre-convert (one launch) ----------------
// k16 blocks: [0,4) W0a | [4,20) W0b | [20,36) Wha | [36,52) Whb
__global__ void wcvt16_all_kernel(const float* __restrict__ W0a,
                                  const float* __restrict__ W0b,
                                  const float* __restrict__ Wha,
                                  const float* __restrict__ Whb,
                                  uint2* __restrict__ out)
{
    int idx = blockIdx.x * blockDim.x + threadIdx.x;
    if (idx >= 52 * 1024) return;
    int tg  = idx & 3;
    int col = (idx >> 2) & 255;
    int k16 = idx >> 10;
    const float* W;
    int lk;
    if (k16 < 4)       { W = W0a; lk = k16; }
    else if (k16 < 20) { W = W0b; lk = k16 - 4; }
    else if (k16 < 36) { W = Wha; lk = k16 - 20; }
    else               { W = Whb; lk = k16 - 36; }
    int kr = lk * 16;
    __half2 lo = __floats2half2_rn(W[(kr + 2 * tg)     * 256 + col],
                                   W[(kr + 2 * tg + 1) * 256 + col]);
    __half2 hi = __floats2half2_rn(W[(kr + 2 * tg + 8) * 256 + col],
                                   W[(kr + 2 * tg + 9) * 256 + col]);
    out[idx] = make_uint2(h2u(lo), h2u(hi));
}

// ---------------- Embedding gather (fp32 table -> fp16 h0) ----------------
__global__ void embed_kernel(const int* __restrict__ x,
                             const float* __restrict__ table,
                             __half* __restrict__ h0)
{
    int idx = blockIdx.x * blockDim.x + threadIdx.x;   // NNODES * 8 (8 halves each)
    if (idx >= NNODES * 8) return;
    int n  = idx >> 3;
    int c8 = idx & 7;
    int b   = n >> 7;
    int col = n & 127;
    int row = x[(b << 7) + col] + col * CARD;
    const float4* src = (const float4*)(table + (size_t)row * 64) + c8 * 2;
    float4 a = __ldg(src);
    float4 c = __ldg(src + 1);
    uint4 o;
    o.x = h2u(__floats2half2_rn(a.x, a.y));
    o.y = h2u(__floats2half2_rn(a.z, a.w));
    o.z = h2u(__floats2half2_rn(c.x, c.y));
    o.w = h2u(__floats2half2_rn(c.z, c.w));
    ((uint4*)h0)[idx] = o;
}

// ---------------- CSR build ----------------
__global__ void hist_kernel(const int* __restrict__ ei, int* __restrict__ deg)
{
    int e = blockIdx.x * blockDim.x + threadIdx.x;
    if (e < NEDGE) atomicAdd(deg + ei[NEDGE + e], 1);
}

__global__ void scan_kernel(const int* __restrict__ deg,
                            int* __restrict__ off, int* __restrict__ cur)
{
    __shared__ int ps[1024];
    const int t = threadIdx.x;
    const int base = t * 128;
    int s = 0;
#pragma unroll 8
    for (int i = 0; i < 128; i++) s += deg[base + i];
    ps[t] = s;
    __syncthreads();
    for (int o = 1; o < 1024; o <<= 1) {
        int v = (t >= o) ? ps[t - o] : 0;
        __syncthreads();
        ps[t] += v;
        __syncthreads();
    }
    int run = ps[t] - s;
#pragma unroll 8
    for (int i = 0; i < 128; i++) {
        int d = deg[base + i];
        off[base + i] = run;
        cur[base + i] = run;
        run += d;
    }
    if (t == 1023) off[NNODES] = run;
}

__global__ void fill_kernel(const int* __restrict__ ei,
                            int* __restrict__ cur, int* __restrict__ srcl)
{
    int e = blockIdx.x * blockDim.x + threadIdx.x;
    if (e >= NEDGE) return;
    int d = ei[NEDGE + e];
    int pos = atomicAdd(cur + d, 1);
    srcl[pos] = ei[e];
}

// ---------------- Fused GIN layer: gather + GEMM1 + LN + GEMM2 (+group reduce) ----
// Block = 512 threads = 16 warps; 64 rows x 256 cols. Warp w owns cols [w*16, w*16+16).
// hin/hout are DISTINCT buffers (ping-pong).
// Staging: warp-uniform node loop + LANE-COOPERATIVE srcl prefetch: the warp loads
//   up to 32 neighbor ids in one coalesced LDG, broadcasts via shfl — removes the
//   srcl load from the row-load dependency chain (MLP=4 over rows only).
// LN: per-warp column partials -> smem -> per-row stats -> normalize in regs -> Af.
// FINAL: epilogue reduces C over the block's 64 rows (one group) -> fp32 d_out.

// SMEM float offsets
#define SPBA   0
#define SPG    256
#define SPB    512
#define AF_OFF 768                  // 8448 words (16 k16 * 4 mt * 33-pad * 4)
#define PS_OFF (768 + 8448)         // 1024 (64 rows x 16 warps)
#define PQ_OFF (PS_OFF + 1024)      // 1024
#define MR_OFF (PQ_OFF + 1024)      // 64
#define IR_OFF (MR_OFF + 64)        // 64
#define GIN_SMEM_F (IR_OFF + 64)

template<int K, bool FINAL>
__global__ void __launch_bounds__(512)
gin_f16_kernel(const int* __restrict__ off, const int* __restrict__ srcl,
               const __half* __restrict__ hin,
               const uint2* __restrict__ Waf, const float* __restrict__ ba,
               const float* __restrict__ gam,  const float* __restrict__ bet,
               const uint2* __restrict__ Wbf, const float* __restrict__ bb,
               const float* __restrict__ epsArr, int layer,
               __half* __restrict__ hout, float* __restrict__ gout)
{
    extern __shared__ float smem[];
    uint32_t* AfU = (uint32_t*)(smem + AF_OFF);

    const int t    = threadIdx.x;
    const int lane = t & 31;
    const int warp = t >> 5;
    const int g    = lane >> 2;
    const int tg   = lane & 3;
    const int wb   = warp * 16;
    const int rowBase = blockIdx.x * 64;

    if (t < 256) { smem[SPBA + t] = ba[t]; smem[SPG + t] = gam[t]; smem[SPB + t] = bet[t]; }

    // ---- Fused gather + stage Af fragments ----
    {
        constexpr int U4R = K / 8;                    // uint4 per feature row
        constexpr int TPN = (U4R < 32) ? U4R : 32;    // threads per node
        constexpr int NPW = 32 / TPN;                 // nodes handled concurrently
        constexpr int NI  = 4 / NPW;                  // serial node iterations per warp
        const uint4* hu = (const uint4*)hin;
        const int sub = lane % TPN;                   // uint4 position within row
        const int nwi = lane / TPN;                   // concurrent node slot
        const float ope = 1.0f + __ldg(epsArr + layer);
        const unsigned gmask = (TPN == 32) ? 0xFFFFFFFFu
                                           : (((1u << TPN) - 1u) << (nwi * TPN));
#pragma unroll
        for (int i = 0; i < NI; i++) {
            const int zrow = warp * 4 + i * NPW + nwi;
            const int node = rowBase + zrow;
            const int beg = __ldg(off + node), end = __ldg(off + node + 1);
            const int mtz = zrow >> 4, rz = zrow & 15, g2z = rz & 7, qrz = rz >> 3;
            const int pos = sub;
            float a[8];
            {
                uint4 v = __ldg(hu + (size_t)node * U4R + pos);
#pragma unroll
                for (int u = 0; u < 4; u++) {
                    float2 f = u2f2((&v.x)[u]);
                    a[2 * u] = ope * f.x; a[2 * u + 1] = ope * f.y;
                }
            }
            // neighbor loop in chunks of TPN ids, prefetched cooperatively
            for (int base = beg; base < end; base += TPN) {
                int rem = end - base;
                int cnt = rem < TPN ? rem : TPN;
                int sv = (sub < cnt) ? __ldg(srcl + base + sub) : 0;
                int j = 0;
                for (; j + 4 <= cnt; j += 4) {
                    int s0 = __shfl_sync(gmask, sv, j,     TPN);
                    int s1 = __shfl_sync(gmask, sv, j + 1, TPN);
                    int s2 = __shfl_sync(gmask, sv, j + 2, TPN);
                    int s3 = __shfl_sync(gmask, sv, j + 3, TPN);
                    uint4 v0 = __ldg(hu + (size_t)s0 * U4R + pos);
                    uint4 v1 = __ldg(hu + (size_t)s1 * U4R + pos);
                    uint4 v2 = __ldg(hu + (size_t)s2 * U4R + pos);
                    uint4 v3 = __ldg(hu + (size_t)s3 * U4R + pos);
#pragma unroll
                    for (int u = 0; u < 4; u++) {
                        float2 f0 = u2f2((&v0.x)[u]), f1 = u2f2((&v1.x)[u]);
                        float2 f2 = u2f2((&v2.x)[u]), f3 = u2f2((&v3.x)[u]);
                        a[2 * u]     += (f0.x + f1.x) + (f2.x + f3.x);
                        a[2 * u + 1] += (f0.y + f1.y) + (f2.y + f3.y);
                    }
                }
                for (; j < cnt; j++) {
                    int s0 = __shfl_sync(gmask, sv, j, TPN);
                    uint4 v = __ldg(hu + (size_t)s0 * U4R + pos);
#pragma unroll
                    for (int u = 0; u < 4; u++) {
                        float2 f = u2f2((&v.x)[u]);
                        a[2 * u] += f.x; a[2 * u + 1] += f.y;
                    }
                }
            }
            int k16 = pos >> 1, hi = pos & 1;
            uint32_t* base2 = AfU + (((k16 * 4 + mtz) * 33) + g2z * 4) * 4 + qrz + 2 * hi;
            base2[0]  = h2u(__floats2half2_rn(a[0], a[1]));
            base2[4]  = h2u(__floats2half2_rn(a[2], a[3]));
            base2[8]  = h2u(__floats2half2_rn(a[4], a[5]));
            base2[12] = h2u(__floats2half2_rn(a[6], a[7]));
        }
    }
    __syncthreads();

    float C[4][2][4];
#pragma unroll
    for (int mt = 0; mt < 4; mt++)
#pragma unroll
        for (int nt = 0; nt < 2; nt++)
#pragma unroll
            for (int q = 0; q < 4; q++) C[mt][nt][q] = 0.0f;

    const int iA = (wb + g) * 4 + tg;
    const int iB = iA + 32;

    // ---- Phase 1: Af @ Waf ----
    {
        constexpr int K16 = K / 16;
        uint2 b0 = __ldg(Waf + iA);
        uint2 b1 = __ldg(Waf + iB);
#pragma unroll
        for (int k16 = 0; k16 < K16; k16++) {
            uint2 n0 = b0, n1 = b1;
            if (k16 + 1 < K16) {
                n0 = __ldg(Waf + (k16 + 1) * 1024 + iA);
                n1 = __ldg(Waf + (k16 + 1) * 1024 + iB);
            }
#pragma unroll
            for (int mt = 0; mt < 4; mt++) {
                uint4 a = *(const uint4*)(AfU + ((k16 * 4 + mt) * 33 + lane) * 4);
                mma_f16(C[mt][0], a, b0.x, b0.y);
                mma_f16(C[mt][1], a, b1.x, b1.y);
            }
            b0 = n0; b1 = n1;
        }
    }

    // ---- LN step 1: per-warp column partials over this warp's 16 cols ----
#pragma unroll
    for (int mt = 0; mt < 4; mt++)
#pragma unroll
        for (int qr = 0; qr < 2; qr++) {
            float s = 0.0f, q2 = 0.0f;
#pragma unroll
            for (int nt = 0; nt < 2; nt++)
#pragma unroll
                for (int lo = 0; lo < 2; lo++) {
                    int col = wb + nt * 8 + 2 * tg + lo;
                    float v = C[mt][nt][2 * qr + lo] + smem[SPBA + col];
                    s += v;
                    q2 = fmaf(v, v, q2);
                }
            s  += __shfl_xor_sync(0xffffffffu, s, 1);
            s  += __shfl_xor_sync(0xffffffffu, s, 2);
            q2 += __shfl_xor_sync(0xffffffffu, q2, 1);
            q2 += __shfl_xor_sync(0xffffffffu, q2, 2);
            if (tg == 0) {
                int row = mt * 16 + g + 8 * qr;
                smem[PS_OFF + row * 16 + warp] = s;
                smem[PQ_OFF + row * 16 + warp] = q2;
            }
        }
    __syncthreads();

    // ---- LN step 2: per-row stats (4 threads/row) ----
    if (t < 256) {
        int row = t >> 2;
        int p4  = t & 3;
        float s = 0.0f, q2 = 0.0f;
#pragma unroll
        for (int i = 0; i < 4; i++) {
            s  += smem[PS_OFF + row * 16 + p4 * 4 + i];
            q2 += smem[PQ_OFF + row * 16 + p4 * 4 + i];
        }
        s  += __shfl_xor_sync(0xffffffffu, s, 1);
        s  += __shfl_xor_sync(0xffffffffu, s, 2);
        q2 += __shfl_xor_sync(0xffffffffu, q2, 1);
        q2 += __shfl_xor_sync(0xffffffffu, q2, 2);
        if (p4 == 0) {
            float mean = s * (1.0f / 256.0f);
            float var  = q2 * (1.0f / 256.0f) - mean * mean;
            smem[MR_OFF + row] = mean;
            smem[IR_OFF + row] = rsqrtf(var + 1e-5f);
        }
    }
    __syncthreads();

    // ---- LN step 3: normalize in registers, write fragments to Af ----
#pragma unroll
    for (int mt = 0; mt < 4; mt++)
#pragma unroll
        for (int qr = 0; qr < 2; qr++) {
            int row = mt * 16 + g + 8 * qr;
            float mean = smem[MR_OFF + row];
            float inv  = smem[IR_OFF + row];
#pragma unroll
            for (int nt = 0; nt < 2; nt++) {
                int c0 = wb + nt * 8 + 2 * tg;
                float v0 = fmaf((C[mt][nt][2 * qr]     + smem[SPBA + c0]     - mean) * inv,
                                smem[SPG + c0],     smem[SPB + c0]);
                float v1 = fmaf((C[mt][nt][2 * qr + 1] + smem[SPBA + c0 + 1] - mean) * inv,
                                smem[SPG + c0 + 1], smem[SPB + c0 + 1]);
                v0 = fmaxf(v0, 0.0f);
                v1 = fmaxf(v1, 0.0f);
                AfU[((warp * 4 + mt) * 33 + g * 4 + tg) * 4 + qr + 2 * nt] =
                    h2u(__floats2half2_rn(v0, v1));
            }
        }
    __syncthreads();

    // ---- Phase 2: Af(=T) @ Wbf ----
#pragma unroll
    for (int mt = 0; mt < 4; mt++)
#pragma unroll
        for (int nt = 0; nt < 2; nt++)
#pragma unroll
            for (int q = 0; q < 4; q++) C[mt][nt][q] = 0.0f;

    {
        uint2 b0 = __ldg(Wbf + iA);
        uint2 b1 = __ldg(Wbf + iB);
#pragma unroll
        for (int k16 = 0; k16 < 16; k16++) {
            uint2 n0 = b0, n1 = b1;
            if (k16 + 1 < 16) {
                n0 = __ldg(Wbf + (k16 + 1) * 1024 + iA);
                n1 = __ldg(Wbf + (k16 + 1) * 1024 + iB);
            }
#pragma unroll
            for (int mt = 0; mt < 4; mt++) {
                uint4 a = *(const uint4*)(AfU + ((k16 * 4 + mt) * 33 + lane) * 4);
                mma_f16(C[mt][0], a, b0.x, b0.y);
                mma_f16(C[mt][1], a, b1.x, b1.y);
            }
            b0 = n0; b1 = n1;
        }
    }

    if (!FINAL) {
        // ---- + bb, store fp16 to global (distinct buffer from hin) ----
        uint32_t* ho = (uint32_t*)hout;
#pragma unroll
        for (int mt = 0; mt < 4; mt++)
#pragma unroll
            for (int nt = 0; nt < 2; nt++) {
                int r0  = rowBase + mt * 16 + g;
                int col = wb + nt * 8 + 2 * tg;
                float2 bbv = *(const float2*)(bb + col);
                __half2 o0 = __floats2half2_rn(C[mt][nt][0] + bbv.x, C[mt][nt][1] + bbv.y);
                __half2 o1 = __floats2half2_rn(C[mt][nt][2] + bbv.x, C[mt][nt][3] + bbv.y);
                ho[(size_t) r0      * 128 + (col >> 1)] = h2u(o0);
                ho[(size_t)(r0 + 8) * 128 + (col >> 1)] = h2u(o1);
            }
    } else {
        // ---- fused group reduction: sum over 64 rows, +64*bb, fp32 out ----
#pragma unroll
        for (int nt = 0; nt < 2; nt++) {
            float s0 = 0.0f, s1 = 0.0f;
#pragma unroll
            for (int mt = 0; mt < 4; mt++) {
                s0 += C[mt][nt][0] + C[mt][nt][2];
                s1 += C[mt][nt][1] + C[mt][nt][3];
            }
#pragma unroll
            for (int o = 4; o <= 16; o <<= 1) {
                s0 += __shfl_xor_sync(0xffffffffu, s0, o);
                s1 += __shfl_xor_sync(0xffffffffu, s1, o);
            }
            if (g == 0) {
                int col = wb + nt * 8 + 2 * tg;
                float2 bbv = *(const float2*)(bb + col);
                float2 o2 = make_float2(s0 + 64.0f * bbv.x, s1 + 64.0f * bbv.y);
                *(float2*)(gout + (size_t)blockIdx.x * 256 + col) = o2;
            }
        }
    }
}

// ---------------- Launch ----------------
extern "C" void kernel_launch(void* const* d_in, const int* in_sizes, int n_in,
                              void* d_out, int out_size)
{
    const int*   x     = (const int*)  d_in[0];
    const int*   ei    = (const int*)  d_in[1];
    const float* table = (const float*)d_in[3];
    const float* W0a   = (const float*)d_in[4];
    const float* b0a   = (const float*)d_in[5];
    const float* g0    = (const float*)d_in[6];
    const float* be0   = (const float*)d_in[7];
    const float* W0b   = (const float*)d_in[8];
    const float* b0b   = (const float*)d_in[9];
    const float* Wha   = (const float*)d_in[10];
    const float* bha   = (const float*)d_in[11];
    const float* gh    = (const float*)d_in[12];
    const float* beh   = (const float*)d_in[13];
    const float* Whb   = (const float*)d_in[14];
    const float* bhb   = (const float*)d_in[15];
    const float* eps   = (const float*)d_in[16];

    __half *h0, *hA, *hB;
    int *deg, *off, *cur, *srcl;
    uint2 *wf;
    cudaGetSymbolAddress((void**)&h0,   g_h0);
    cudaGetSymbolAddress((void**)&hA,   g_hA);
    cudaGetSymbolAddress((void**)&hB,   g_hB);
    cudaGetSymbolAddress((void**)&deg,  g_deg);
    cudaGetSymbolAddress((void**)&off,  g_off);
    cudaGetSymbolAddress((void**)&cur,  g_cur);
    cudaGetSymbolAddress((void**)&srcl, g_srcl);
    cudaGetSymbolAddress((void**)&wf,   g_wf16);

    uint2* W0af = wf;               // 4 k16 blocks
    uint2* W0bf = wf + 4  * 1024;   // 16
    uint2* Whaf = wf + 20 * 1024;   // 16
    uint2* Whbf = wf + 36 * 1024;   // 16

    const int SMEM_BYTES = GIN_SMEM_F * (int)sizeof(float);
    cudaFuncSetAttribute((const void*)gin_f16_kernel<64, false>,
                         cudaFuncAttributeMaxDynamicSharedMemorySize, SMEM_BYTES);
    cudaFuncSetAttribute((const void*)gin_f16_kernel<256, false>,
                         cudaFuncAttributeMaxDynamicSharedMemorySize, SMEM_BYTES);
    cudaFuncSetAttribute((const void*)gin_f16_kernel<256, true>,
                         cudaFuncAttributeMaxDynamicSharedMemorySize, SMEM_BYTES);

    // ---- Weight pre-convert (fp16 fragment order, single launch) ----
    wcvt16_all_kernel<<<(52 * 1024 + 255) / 256, 256>>>(W0a, W0b, Wha, Whb, wf);

    // ---- CSR build ----
    cudaMemsetAsync(deg, 0, (NNODES + 1) * sizeof(int));
    hist_kernel<<<(NEDGE + 255) / 256, 256>>>(ei, deg);
    scan_kernel<<<1, 1024>>>(deg, off, cur);
    fill_kernel<<<(NEDGE + 255) / 256, 256>>>(ei, cur, srcl);

    // ---- Embedding gather ----
    embed_kernel<<<(NNODES * 8 + 255) / 256, 256>>>(x, table, h0);

    // ---- Layer 0 (K = 64, gather fused): h0 -> hA ----
    gin_f16_kernel<64, false><<<NNODES / 64, 512, SMEM_BYTES>>>(
        off, srcl, h0, W0af, b0a, g0, be0, W0bf, b0b, eps, 0, hA, nullptr);

    // ---- Layer 1 (K = 256, gather fused): hA -> hB ----
    gin_f16_kernel<256, false><<<NNODES / 64, 512, SMEM_BYTES>>>(
        off, srcl, hA, Whaf, bha, gh, beh, Whbf, bhb, eps, 1, hB, nullptr);

    // ---- Layer 2 (K = 256): hB -> d_out (fused group reduction) ----
    gin_f16_kernel<256, true><<<NNODES / 64, 512, SMEM_BYTES>>>(
        off, srcl, hB, Whaf, bha, gh, beh, Whbf, bhb, eps, 2, nullptr, (float*)d_out);
}

// round 17
// speedup vs baseline: 1.2027x; 1.0156x over previous
#include <cuda_runtime.h>
#include <cuda_fp16.h>
#include <cstddef>
#include <cstdint>

// ---------------- Problem constants ----------------
#define NNODES   131072        // B*2*NN
#define HDIM     256
#define EMBD     64
#define NEDGE    1000000
#define NGROUP   2048          // B*2
#define CARD     100

// ---------------- Scratch (no allocs allowed) ----------------
__device__ __align__(16) __half g_h0 [NNODES * EMBD];
__device__ __align__(16) __half g_hA [NNODES * HDIM];  // ping
__device__ __align__(16) __half g_hB [NNODES * HDIM];  // pong
__device__ int   g_deg[NNODES + 1];
__device__ int   g_off[NNODES + 1];
__device__ int   g_cur[NNODES];
__device__ int   g_srcl[NEDGE];
// fp16 fragment-ordered weights: per k16 block: 256 cols x 4 tg, uint2 {lo-pair, hi-pair}
__device__ uint2 g_wf16[(4 + 16 + 16 + 16) * 1024];

// ---------------- Helpers ----------------
__device__ __forceinline__ uint32_t h2u(__half2 h) {
    return *reinterpret_cast<uint32_t*>(&h);
}
__device__ __forceinline__ float2 u2f2(uint32_t u) {
    return __half22float2(*reinterpret_cast<__half2*>(&u));
}

__device__ __forceinline__ void mma_f16(float (&c)[4], const uint4& a,
                                        uint32_t b0, uint32_t b1) {
    asm volatile(
        "mma.sync.aligned.m16n8k16.row.col.f32.f16.f16.f32 "
        "{%0,%1,%2,%3}, {%4,%5,%6,%7}, {%8,%9}, {%0,%1,%2,%3};"
        : "+f"(c[0]), "+f"(c[1]), "+f"(c[2]), "+f"(c[3])
        : "r"(a.x), "r"(a.y), "r"(a.z), "r"(a.w), "r"(b0), "r"(b1));
}

// ---------------- Merged weight pre-convert (one launch) ----------------
// k16 blocks: [0,4) W0a | [4,20) W0b | [20,36) Wha | [36,52) Whb
__global__ void wcvt16_all_kernel(const float* __restrict__ W0a,
                                  const float* __restrict__ W0b,
                                  const float* __restrict__ Wha,
                                  const float* __restrict__ Whb,
                                  uint2* __restrict__ out)
{
    int idx = blockIdx.x * blockDim.x + threadIdx.x;
    if (idx >= 52 * 1024) return;
    int tg  = idx & 3;
    int col = (idx >> 2) & 255;
    int k16 = idx >> 10;
    const float* W;
    int lk;
    if (k16 < 4)       { W = W0a; lk = k16; }
    else if (k16 < 20) { W = W0b; lk = k16 - 4; }
    else if (k16 < 36) { W = Wha; lk = k16 - 20; }
    else               { W = Whb; lk = k16 - 36; }
    int kr = lk * 16;
    __half2 lo = __floats2half2_rn(W[(kr + 2 * tg)     * 256 + col],
                                   W[(kr + 2 * tg + 1) * 256 + col]);
    __half2 hi = __floats2half2_rn(W[(kr + 2 * tg + 8) * 256 + col],
                                   W[(kr + 2 * tg + 9) * 256 + col]);
    out[idx] = make_uint2(h2u(lo), h2u(hi));
}

// ---------------- Embedding gather (fp32 table -> fp16 h0) ----------------
__global__ void embed_kernel(const int* __restrict__ x,
                             const float* __restrict__ table,
                             __half* __restrict__ h0)
{
    int idx = blockIdx.x * blockDim.x + threadIdx.x;   // NNODES * 8 (8 halves each)
    if (idx >= NNODES * 8) return;
    int n  = idx >> 3;
    int c8 = idx & 7;
    int b   = n >> 7;
    int col = n & 127;
    int row = x[(b << 7) + col] + col * CARD;
    const float4* src = (const float4*)(table + (size_t)row * 64) + c8 * 2;
    float4 a = __ldg(src);
    float4 c = __ldg(src + 1);
    uint4 o;
    o.x = h2u(__floats2half2_rn(a.x, a.y));
    o.y = h2u(__floats2half2_rn(a.z, a.w));
    o.z = h2u(__floats2half2_rn(c.x, c.y));
    o.w = h2u(__floats2half2_rn(c.z, c.w));
    ((uint4*)h0)[idx] = o;
}

// ---------------- CSR build ----------------
__global__ void hist_kernel(const int* __restrict__ ei, int* __restrict__ deg)
{
    int e = blockIdx.x * blockDim.x + threadIdx.x;
    if (e < NEDGE) atomicAdd(deg + ei[NEDGE + e], 1);
}

__global__ void scan_kernel(const int* __restrict__ deg,
                            int* __restrict__ off, int* __restrict__ cur)
{
    __shared__ int ps[1024];
    const int t = threadIdx.x;
    const int base = t * 128;
    int s = 0;
#pragma unroll 8
    for (int i = 0; i < 128; i++) s += deg[base + i];
    ps[t] = s;
    __syncthreads();
    for (int o = 1; o < 1024; o <<= 1) {
        int v = (t >= o) ? ps[t - o] : 0;
        __syncthreads();
        ps[t] += v;
        __syncthreads();
    }
    int run = ps[t] - s;
#pragma unroll 8
    for (int i = 0; i < 128; i++) {
        int d = deg[base + i];
        off[base + i] = run;
        cur[base + i] = run;
        run += d;
    }
    if (t == 1023) off[NNODES] = run;
}

__global__ void fill_kernel(const int* __restrict__ ei,
                            int* __restrict__ cur, int* __restrict__ srcl)
{
    int e = blockIdx.x * blockDim.x + threadIdx.x;
    if (e >= NEDGE) return;
    int d = ei[NEDGE + e];
    int pos = atomicAdd(cur + d, 1);
    srcl[pos] = ei[e];
}

// ---------------- Fused GIN layer, 256 threads / 32 rows (multi-CTA/SM) ----------
// Block = 256 threads = 8 warps; 32 rows x 256 cols. Warp w owns cols [w*32, w*32+32)
// (nt = 0..3 n-tiles of 8; mt = 0..1 m-tiles of 16). ~22KB SMEM -> 2-3 CTAs/SM so
// one CTA's gather-staging overlaps another's mma/LN phases.
// Staging: warp-uniform node loop + lane-cooperative srcl prefetch (as R16 best).
// FINAL: block covers HALF a group (32 rows); partial sums (+32*bb) are atomicAdd'ed
// into zero-initialized d_out.

// SMEM float offsets
#define SPBA   0
#define SPG    256
#define SPB    512
#define AF_OFF 768                  // 4224 words (16 k16 * 2 mt * 33-pad * 4)
#define PS_OFF (768 + 4224)         // 256 (32 rows x 8 warps)
#define PQ_OFF (PS_OFF + 256)       // 256
#define MR_OFF (PQ_OFF + 256)       // 32
#define IR_OFF (MR_OFF + 32)        // 32
#define GIN_SMEM_F (IR_OFF + 32)

template<int K, bool FINAL>
__global__ void __launch_bounds__(256)
gin_f16_kernel(const int* __restrict__ off, const int* __restrict__ srcl,
               const __half* __restrict__ hin,
               const uint2* __restrict__ Waf, const float* __restrict__ ba,
               const float* __restrict__ gam,  const float* __restrict__ bet,
               const uint2* __restrict__ Wbf, const float* __restrict__ bb,
               const float* __restrict__ epsArr, int layer,
               __half* __restrict__ hout, float* __restrict__ gout)
{
    extern __shared__ float smem[];
    uint32_t* AfU = (uint32_t*)(smem + AF_OFF);

    const int t    = threadIdx.x;
    const int lane = t & 31;
    const int warp = t >> 5;              // 0..7
    const int g    = lane >> 2;
    const int tg   = lane & 3;
    const int wb   = warp * 32;           // warp column base
    const int rowBase = blockIdx.x * 32;

    smem[SPBA + t] = ba[t]; smem[SPG + t] = gam[t]; smem[SPB + t] = bet[t];

    // ---- Fused gather + stage Af fragments ----
    {
        constexpr int U4R = K / 8;                    // uint4 per feature row
        constexpr int TPN = (U4R < 32) ? U4R : 32;    // threads per node
        constexpr int NPW = 32 / TPN;                 // nodes handled concurrently
        constexpr int NI  = 4 / NPW;                  // serial node iterations per warp
        const uint4* hu = (const uint4*)hin;
        const int sub = lane % TPN;
        const int nwi = lane / TPN;
        const float ope = 1.0f + __ldg(epsArr + layer);
        const unsigned gmask = (TPN == 32) ? 0xFFFFFFFFu
                                           : (((1u << TPN) - 1u) << (nwi * TPN));
#pragma unroll
        for (int i = 0; i < NI; i++) {
            const int zrow = warp * 4 + i * NPW + nwi;   // 0..31
            const int node = rowBase + zrow;
            const int beg = __ldg(off + node), end = __ldg(off + node + 1);
            const int mtz = zrow >> 4, rz = zrow & 15, g2z = rz & 7, qrz = rz >> 3;
            const int pos = sub;
            float a[8];
            {
                uint4 v = __ldg(hu + (size_t)node * U4R + pos);
#pragma unroll
                for (int u = 0; u < 4; u++) {
                    float2 f = u2f2((&v.x)[u]);
                    a[2 * u] = ope * f.x; a[2 * u + 1] = ope * f.y;
                }
            }
            for (int base = beg; base < end; base += TPN) {
                int rem = end - base;
                int cnt = rem < TPN ? rem : TPN;
                int sv = (sub < cnt) ? __ldg(srcl + base + sub) : 0;
                int j = 0;
                for (; j + 4 <= cnt; j += 4) {
                    int s0 = __shfl_sync(gmask, sv, j,     TPN);
                    int s1 = __shfl_sync(gmask, sv, j + 1, TPN);
                    int s2 = __shfl_sync(gmask, sv, j + 2, TPN);
                    int s3 = __shfl_sync(gmask, sv, j + 3, TPN);
                    uint4 v0 = __ldg(hu + (size_t)s0 * U4R + pos);
                    uint4 v1 = __ldg(hu + (size_t)s1 * U4R + pos);
                    uint4 v2 = __ldg(hu + (size_t)s2 * U4R + pos);
                    uint4 v3 = __ldg(hu + (size_t)s3 * U4R + pos);
#pragma unroll
                    for (int u = 0; u < 4; u++) {
                        float2 f0 = u2f2((&v0.x)[u]), f1 = u2f2((&v1.x)[u]);
                        float2 f2 = u2f2((&v2.x)[u]), f3 = u2f2((&v3.x)[u]);
                        a[2 * u]     += (f0.x + f1.x) + (f2.x + f3.x);
                        a[2 * u + 1] += (f0.y + f1.y) + (f2.y + f3.y);
                    }
                }
                for (; j < cnt; j++) {
                    int s0 = __shfl_sync(gmask, sv, j, TPN);
                    uint4 v = __ldg(hu + (size_t)s0 * U4R + pos);
#pragma unroll
                    for (int u = 0; u < 4; u++) {
                        float2 f = u2f2((&v.x)[u]);
                        a[2 * u] += f.x; a[2 * u + 1] += f.y;
                    }
                }
            }
            int k16 = pos >> 1, hi = pos & 1;
            uint32_t* base2 = AfU + (((k16 * 2 + mtz) * 33) + g2z * 4) * 4 + qrz + 2 * hi;
            base2[0]  = h2u(__floats2half2_rn(a[0], a[1]));
            base2[4]  = h2u(__floats2half2_rn(a[2], a[3]));
            base2[8]  = h2u(__floats2half2_rn(a[4], a[5]));
            base2[12] = h2u(__floats2half2_rn(a[6], a[7]));
        }
    }
    __syncthreads();

    float C[2][4][4];
#pragma unroll
    for (int mt = 0; mt < 2; mt++)
#pragma unroll
        for (int nt = 0; nt < 4; nt++)
#pragma unroll
            for (int q = 0; q < 4; q++) C[mt][nt][q] = 0.0f;

    int iN[4];
#pragma unroll
    for (int nt = 0; nt < 4; nt++) iN[nt] = (wb + nt * 8 + g) * 4 + tg;

    // ---- Phase 1: Af @ Waf ----
    {
        constexpr int K16 = K / 16;
        uint2 b[4], n[4];
#pragma unroll
        for (int nt = 0; nt < 4; nt++) b[nt] = __ldg(Waf + iN[nt]);
#pragma unroll
        for (int k16 = 0; k16 < K16; k16++) {
#pragma unroll
            for (int nt = 0; nt < 4; nt++)
                n[nt] = (k16 + 1 < K16) ? __ldg(Waf + (k16 + 1) * 1024 + iN[nt]) : b[nt];
#pragma unroll
            for (int mt = 0; mt < 2; mt++) {
                uint4 a = *(const uint4*)(AfU + ((k16 * 2 + mt) * 33 + lane) * 4);
#pragma unroll
                for (int nt = 0; nt < 4; nt++) mma_f16(C[mt][nt], a, b[nt].x, b[nt].y);
            }
#pragma unroll
            for (int nt = 0; nt < 4; nt++) b[nt] = n[nt];
        }
    }

    // ---- LN step 1: per-warp column partials over this warp's 32 cols ----
#pragma unroll
    for (int mt = 0; mt < 2; mt++)
#pragma unroll
        for (int qr = 0; qr < 2; qr++) {
            float s = 0.0f, q2 = 0.0f;
#pragma unroll
            for (int nt = 0; nt < 4; nt++)
#pragma unroll
                for (int lo = 0; lo < 2; lo++) {
                    int col = wb + nt * 8 + 2 * tg + lo;
                    float v = C[mt][nt][2 * qr + lo] + smem[SPBA + col];
                    s += v;
                    q2 = fmaf(v, v, q2);
                }
            s  += __shfl_xor_sync(0xffffffffu, s, 1);
            s  += __shfl_xor_sync(0xffffffffu, s, 2);
            q2 += __shfl_xor_sync(0xffffffffu, q2, 1);
            q2 += __shfl_xor_sync(0xffffffffu, q2, 2);
            if (tg == 0) {
                int row = mt * 16 + g + 8 * qr;
                smem[PS_OFF + row * 8 + warp] = s;
                smem[PQ_OFF + row * 8 + warp] = q2;
            }
        }
    __syncthreads();

    // ---- LN step 2: per-row stats (8 threads/row, shfl within 8-lane groups) ----
    {
        int row = t >> 3;                 // 0..31
        int p8  = t & 7;
        float s  = smem[PS_OFF + row * 8 + p8];
        float q2 = smem[PQ_OFF + row * 8 + p8];
        s  += __shfl_xor_sync(0xffffffffu, s, 1);
        s  += __shfl_xor_sync(0xffffffffu, s, 2);
        s  += __shfl_xor_sync(0xffffffffu, s, 4);
        q2 += __shfl_xor_sync(0xffffffffu, q2, 1);
        q2 += __shfl_xor_sync(0xffffffffu, q2, 2);
        q2 += __shfl_xor_sync(0xffffffffu, q2, 4);
        if (p8 == 0) {
            float mean = s * (1.0f / 256.0f);
            float var  = q2 * (1.0f / 256.0f) - mean * mean;
            smem[MR_OFF + row] = mean;
            smem[IR_OFF + row] = rsqrtf(var + 1e-5f);
        }
    }
    __syncthreads();

    // ---- LN step 3: normalize in registers, write fragments to Af ----
#pragma unroll
    for (int mt = 0; mt < 2; mt++)
#pragma unroll
        for (int qr = 0; qr < 2; qr++) {
            int row = mt * 16 + g + 8 * qr;
            float mean = smem[MR_OFF + row];
            float inv  = smem[IR_OFF + row];
#pragma unroll
            for (int nt = 0; nt < 4; nt++) {
                int c0 = wb + nt * 8 + 2 * tg;
                float v0 = fmaf((C[mt][nt][2 * qr]     + smem[SPBA + c0]     - mean) * inv,
                                smem[SPG + c0],     smem[SPB + c0]);
                float v1 = fmaf((C[mt][nt][2 * qr + 1] + smem[SPBA + c0 + 1] - mean) * inv,
                                smem[SPG + c0 + 1], smem[SPB + c0 + 1]);
                v0 = fmaxf(v0, 0.0f);
                v1 = fmaxf(v1, 0.0f);
                int k16 = warp * 2 + (nt >> 1);
                int hi  = nt & 1;
                AfU[((k16 * 2 + mt) * 33 + g * 4 + tg) * 4 + qr + 2 * hi] =
                    h2u(__floats2half2_rn(v0, v1));
            }
        }
    __syncthreads();

    // ---- Phase 2: Af(=T) @ Wbf ----
#pragma unroll
    for (int mt = 0; mt < 2; mt++)
#pragma unroll
        for (int nt = 0; nt < 4; nt++)
#pragma unroll
            for (int q = 0; q < 4; q++) C[mt][nt][q] = 0.0f;

    {
        uint2 b[4], n[4];
#pragma unroll
        for (int nt = 0; nt < 4; nt++) b[nt] = __ldg(Wbf + iN[nt]);
#pragma unroll
        for (int k16 = 0; k16 < 16; k16++) {
#pragma unroll
            for (int nt = 0; nt < 4; nt++)
                n[nt] = (k16 + 1 < 16) ? __ldg(Wbf + (k16 + 1) * 1024 + iN[nt]) : b[nt];
#pragma unroll
            for (int mt = 0; mt < 2; mt++) {
                uint4 a = *(const uint4*)(AfU + ((k16 * 2 + mt) * 33 + lane) * 4);
#pragma unroll
                for (int nt = 0; nt < 4; nt++) mma_f16(C[mt][nt], a, b[nt].x, b[nt].y);
            }
#pragma unroll
            for (int nt = 0; nt < 4; nt++) b[nt] = n[nt];
        }
    }

    if (!FINAL) {
        // ---- + bb, store fp16 to global (distinct buffer from hin) ----
        uint32_t* ho = (uint32_t*)hout;
#pragma unroll
        for (int mt = 0; mt < 2; mt++)
#pragma unroll
            for (int nt = 0; nt < 4; nt++) {
                int r0  = rowBase + mt * 16 + g;
                int col = wb + nt * 8 + 2 * tg;
                float2 bbv = *(const float2*)(bb + col);
                __half2 o0 = __floats2half2_rn(C[mt][nt][0] + bbv.x, C[mt][nt][1] + bbv.y);
                __half2 o1 = __floats2half2_rn(C[mt][nt][2] + bbv.x, C[mt][nt][3] + bbv.y);
                ho[(size_t) r0      * 128 + (col >> 1)] = h2u(o0);
                ho[(size_t)(r0 + 8) * 128 + (col >> 1)] = h2u(o1);
            }
    } else {
        // ---- fused half-group reduction: sum over 32 rows, +32*bb, atomicAdd fp32 ----
        const int group = blockIdx.x >> 1;
#pragma unroll
        for (int nt = 0; nt < 4; nt++) {
            float s0 = 0.0f, s1 = 0.0f;
#pragma unroll
            for (int mt = 0; mt < 2; mt++) {
                s0 += C[mt][nt][0] + C[mt][nt][2];
                s1 += C[mt][nt][1] + C[mt][nt][3];
            }
#pragma unroll
            for (int o = 4; o <= 16; o <<= 1) {
                s0 += __shfl_xor_sync(0xffffffffu, s0, o);
                s1 += __shfl_xor_sync(0xffffffffu, s1, o);
            }
            if (g == 0) {
                int col = wb + nt * 8 + 2 * tg;
                float2 bbv = *(const float2*)(bb + col);
                atomicAdd(gout + (size_t)group * 256 + col,     s0 + 32.0f * bbv.x);
                atomicAdd(gout + (size_t)group * 256 + col + 1, s1 + 32.0f * bbv.y);
            }
        }
    }
}

// ---------------- Launch ----------------
extern "C" void kernel_launch(void* const* d_in, const int* in_sizes, int n_in,
                              void* d_out, int out_size)
{
    const int*   x     = (const int*)  d_in[0];
    const int*   ei    = (const int*)  d_in[1];
    const float* table = (const float*)d_in[3];
    const float* W0a   = (const float*)d_in[4];
    const float* b0a   = (const float*)d_in[5];
    const float* g0    = (const float*)d_in[6];
    const float* be0   = (const float*)d_in[7];
    const float* W0b   = (const float*)d_in[8];
    const float* b0b   = (const float*)d_in[9];
    const float* Wha   = (const float*)d_in[10];
    const float* bha   = (const float*)d_in[11];
    const float* gh    = (const float*)d_in[12];
    const float* beh   = (const float*)d_in[13];
    const float* Whb   = (const float*)d_in[14];
    const float* bhb   = (const float*)d_in[15];
    const float* eps   = (const float*)d_in[16];

    __half *h0, *hA, *hB;
    int *deg, *off, *cur, *srcl;
    uint2 *wf;
    cudaGetSymbolAddress((void**)&h0,   g_h0);
    cudaGetSymbolAddress((void**)&hA,   g_hA);
    cudaGetSymbolAddress((void**)&hB,   g_hB);
    cudaGetSymbolAddress((void**)&deg,  g_deg);
    cudaGetSymbolAddress((void**)&off,  g_off);
    cudaGetSymbolAddress((void**)&cur,  g_cur);
    cudaGetSymbolAddress((void**)&srcl, g_srcl);
    cudaGetSymbolAddress((void**)&wf,   g_wf16);

    uint2* W0af = wf;               // 4 k16 blocks
    uint2* W0bf = wf + 4  * 1024;   // 16
    uint2* Whaf = wf + 20 * 1024;   // 16
    uint2* Whbf = wf + 36 * 1024;   // 16

    const int SMEM_BYTES = GIN_SMEM_F * (int)sizeof(float);   // ~22.3 KB

    // ---- Weight pre-convert (fp16 fragment order, single launch) ----
    wcvt16_all_kernel<<<(52 * 1024 + 255) / 256, 256>>>(W0a, W0b, Wha, Whb, wf);

    // ---- CSR build ----
    cudaMemsetAsync(deg, 0, (NNODES + 1) * sizeof(int));
    hist_kernel<<<(NEDGE + 255) / 256, 256>>>(ei, deg);
    scan_kernel<<<1, 1024>>>(deg, off, cur);
    fill_kernel<<<(NEDGE + 255) / 256, 256>>>(ei, cur, srcl);

    // ---- Embedding gather ----
    embed_kernel<<<(NNODES * 8 + 255) / 256, 256>>>(x, table, h0);

    // ---- Layer 0 (K = 64, gather fused): h0 -> hA ----
    gin_f16_kernel<64, false><<<NNODES / 32, 256, SMEM_BYTES>>>(
        off, srcl, h0, W0af, b0a, g0, be0, W0bf, b0b, eps, 0, hA, nullptr);

    // ---- Layer 1 (K = 256, gather fused): hA -> hB ----
    gin_f16_kernel<256, false><<<NNODES / 32, 256, SMEM_BYTES>>>(
        off, srcl, hA, Whaf, bha, gh, beh, Whbf, bhb, eps, 1, hB, nullptr);

    // ---- Layer 2 (K = 256): hB -> d_out (half-group partials + atomics) ----
    cudaMemsetAsync(d_out, 0, (size_t)NGROUP * HDIM * sizeof(float));
    gin_f16_kernel<256, true><<<NNODES / 32, 256, SMEM_BYTES>>>(
        off, srcl, hB, Whaf, bha, gh, beh, Whbf, bhb, eps, 2, nullptr, (float*)d_out);
}